// round 1
// baseline (speedup 1.0000x reference)
#include <cuda_runtime.h>
#include <math.h>
#include <float.h>

#define NROWS 16384      // B*N
#define NPTS  4096
#define KNN   16
#define RTOT  (NROWS*KNN)   // 262144

// ---------------- scratch (static device allocations) ----------------
__device__ float g_hpre[NROWS*64];
__device__ float g_h[NROWS*64];       // post-bn1 relu (= residual)
__device__ float g_qkv[NROWS*192];
__device__ int   g_idx[NROWS*KNN];
__device__ float g_T[RTOT*64];
__device__ float g_vv[RTOT*64];
__device__ float g_sim[RTOT*64];
__device__ float g_agg[NROWS*64];
__device__ float g_u[NROWS*64];
__device__ float g_ypre[NROWS*64];
__device__ float g_mu[64];
__device__ float g_rs[64];

// ---------------- generic 64-K GEMM: C[R,NC] = A[R,64] @ W[64,NC] (+bias) ----
__global__ __launch_bounds__(256) void gemm64_kernel(
    const float* __restrict__ A, const float* __restrict__ W,
    const float* __restrict__ bias, float* __restrict__ Cout, int NC)
{
    __shared__ float As[64*68];
    __shared__ float Ws[64*68];
    int tid = threadIdx.x;
    int rowBase = blockIdx.x * 64;
    int colBase = blockIdx.y * 64;
    for (int i = tid; i < 4096; i += 256) {
        int r = i >> 6, c = i & 63;
        As[r*68 + c] = A[(rowBase + r)*64 + c];
        Ws[r*68 + c] = W[r*NC + colBase + c];
    }
    __syncthreads();
    int rg = tid >> 4, cg = tid & 15;
    float acc[4][4];
    #pragma unroll
    for (int j = 0; j < 4; j++)
        #pragma unroll
        for (int i = 0; i < 4; i++) acc[j][i] = 0.f;
    #pragma unroll 4
    for (int k = 0; k < 64; k++) {
        float a[4];
        #pragma unroll
        for (int j = 0; j < 4; j++) a[j] = As[(rg*4 + j)*68 + k];
        float4 w = *(const float4*)&Ws[k*68 + cg*4];
        #pragma unroll
        for (int j = 0; j < 4; j++) {
            acc[j][0] += a[j]*w.x;
            acc[j][1] += a[j]*w.y;
            acc[j][2] += a[j]*w.z;
            acc[j][3] += a[j]*w.w;
        }
    }
    #pragma unroll
    for (int j = 0; j < 4; j++) {
        int r = rowBase + rg*4 + j;
        #pragma unroll
        for (int i = 0; i < 4; i++) {
            float v = acc[j][i];
            if (bias) v += bias[colBase + cg*4 + i];
            Cout[r*NC + colBase + cg*4 + i] = v;
        }
    }
}

// ---------------- BN stats: one block per channel (deterministic) ----------
__global__ void bn_stats_kernel(const float* __restrict__ src)
{
    int c = blockIdx.x;
    float s1 = 0.f, s2 = 0.f;
    for (int r = threadIdx.x; r < NROWS; r += 256) {
        float v = src[r*64 + c];
        s1 += v; s2 += v*v;
    }
    __shared__ float sh1[256], sh2[256];
    sh1[threadIdx.x] = s1; sh2[threadIdx.x] = s2;
    __syncthreads();
    for (int st = 128; st > 0; st >>= 1) {
        if (threadIdx.x < st) {
            sh1[threadIdx.x] += sh1[threadIdx.x + st];
            sh2[threadIdx.x] += sh2[threadIdx.x + st];
        }
        __syncthreads();
    }
    if (threadIdx.x == 0) {
        float m = sh1[0] / (float)NROWS;
        float var = sh2[0] / (float)NROWS - m*m;
        g_mu[c] = m;
        g_rs[c] = rsqrtf(var + 1e-5f);
    }
}

// ---------------- BN apply + relu (+ optional residual add) ----------------
__global__ void bn_apply_kernel(const float* __restrict__ src,
                                const float* __restrict__ addsrc,
                                const float* __restrict__ gam,
                                const float* __restrict__ bet,
                                float* __restrict__ dst)
{
    int i = blockIdx.x * 256 + threadIdx.x;
    int c = i & 63;
    float v = (src[i] - g_mu[c]) * g_rs[c] * gam[c] + bet[c];
    v = fmaxf(v, 0.f);
    if (addsrc) v += addsrc[i];
    dst[i] = v;
}

// ---------------- brute-force KNN (per-warp query, SMEM point cloud) -------
__global__ __launch_bounds__(256) void knn_kernel(const float* __restrict__ p)
{
    int b = blockIdx.y;
    extern __shared__ float sh[];
    float* px = sh;
    float* py = sh + NPTS;
    float* pz = sh + 2*NPTS;
    float* sd = sh + 3*NPTS;           // 8 warps * 512 floats
    int*   si = (int*)(sd + 8*512);    // 8 warps * 512 ints
    const float* pb = p + b*NPTS*3;
    for (int i = threadIdx.x; i < NPTS; i += 256) {
        px[i] = pb[3*i];
        py[i] = pb[3*i + 1];
        pz[i] = pb[3*i + 2];
    }
    __syncthreads();
    int w = threadIdx.x >> 5, lane = threadIdx.x & 31;
    float* wd = sd + w*512;
    int*   wi = si + w*512;

    for (int qq = 0; qq < 4; qq++) {
        int n = blockIdx.x*32 + w*4 + qq;
        float qx = px[n], qy = py[n], qz = pz[n];
        float dk[16]; int ik[16];
        #pragma unroll
        for (int t = 0; t < 16; t++) { dk[t] = FLT_MAX; ik[t] = 0; }
        for (int m = lane; m < NPTS; m += 32) {
            float dx = px[m]-qx, dy = py[m]-qy, dz = pz[m]-qz;
            float d = dx*dx + dy*dy + dz*dz;
            if (d < dk[15]) {
                dk[15] = d; ik[15] = m;
                #pragma unroll
                for (int s = 15; s > 0; --s) {
                    if (dk[s] < dk[s-1]) {
                        float td = dk[s]; dk[s] = dk[s-1]; dk[s-1] = td;
                        int   ti = ik[s]; ik[s] = ik[s-1]; ik[s-1] = ti;
                    }
                }
            }
        }
        #pragma unroll
        for (int t = 0; t < 16; t++) {
            wd[lane*16 + t] = dk[t];
            wi[lane*16 + t] = ik[t];
        }
        __syncwarp();
        // merge 32 sorted lists of 16 -> global top-16
        int pos = 0;
        for (int t = 0; t < 16; t++) {
            float h = (pos < 16) ? wd[lane*16 + pos] : FLT_MAX;
            float v = h; int src = lane;
            #pragma unroll
            for (int off = 16; off > 0; off >>= 1) {
                float v2 = __shfl_down_sync(0xffffffffu, v, off);
                int   s2 = __shfl_down_sync(0xffffffffu, src, off);
                if (v2 < v || (v2 == v && s2 < src)) { v = v2; src = s2; }
            }
            src = __shfl_sync(0xffffffffu, src, 0);
            int wpos = __shfl_sync(0xffffffffu, pos, src);
            if (lane == 0) g_idx[((long)b*NPTS + n)*16 + t] = wi[src*16 + wpos];
            if (lane == src) pos++;
        }
        __syncwarp();
    }
}

// ---------------- pe-MLP + build T = q - k_j + pe, vv = v_j + pe -----------
__global__ __launch_bounds__(256) void build_t_kernel(
    const float* __restrict__ p,
    const float* __restrict__ w1, const float* __restrict__ b1,
    const float* __restrict__ w2, const float* __restrict__ b2)
{
    __shared__ float sw1[96], sb1[32], sw2[2048], sb2[64];
    int tid = threadIdx.x;
    if (tid < 96) sw1[tid] = w1[tid];
    if (tid < 32) sb1[tid] = b1[tid];
    for (int i = tid; i < 2048; i += 256) sw2[i] = w2[i];
    if (tid < 64) sb2[tid] = b2[tid];
    __syncthreads();

    int rid = tid >> 2, ch = (tid & 3) * 16;
    int row = blockIdx.x * 64 + rid;       // (b,n,j) flattened
    int q = row >> 4;                      // b*4096+n
    int b = q >> 12;
    int nb = (b << 12) + g_idx[row];       // b*4096 + neighbor

    float rx = p[q*3+0] - p[nb*3+0];
    float ry = p[q*3+1] - p[nb*3+1];
    float rz = p[q*3+2] - p[nb*3+2];

    float hid[32];
    #pragma unroll
    for (int h = 0; h < 32; h++) {
        float t = rx*sw1[h] + ry*sw1[32+h] + rz*sw1[64+h] + sb1[h];
        hid[h] = fmaxf(t, 0.f);
    }

    float qvf[16], kjf[16], vjf[16];
    #pragma unroll
    for (int v4 = 0; v4 < 4; v4++) {
        float4 t1 = *(const float4*)&g_qkv[q*192 + ch + v4*4];
        float4 t2 = *(const float4*)&g_qkv[nb*192 + 64 + ch + v4*4];
        float4 t3 = *(const float4*)&g_qkv[nb*192 + 128 + ch + v4*4];
        qvf[v4*4+0]=t1.x; qvf[v4*4+1]=t1.y; qvf[v4*4+2]=t1.z; qvf[v4*4+3]=t1.w;
        kjf[v4*4+0]=t2.x; kjf[v4*4+1]=t2.y; kjf[v4*4+2]=t2.z; kjf[v4*4+3]=t2.w;
        vjf[v4*4+0]=t3.x; vjf[v4*4+1]=t3.y; vjf[v4*4+2]=t3.z; vjf[v4*4+3]=t3.w;
    }

    float To[16], Vo[16];
    #pragma unroll
    for (int cc = 0; cc < 16; cc++) {
        float pe = sb2[ch + cc];
        #pragma unroll
        for (int h = 0; h < 32; h++) pe += hid[h] * sw2[h*64 + ch + cc];
        To[cc] = qvf[cc] - kjf[cc] + pe;
        Vo[cc] = vjf[cc] + pe;
    }
    #pragma unroll
    for (int v4 = 0; v4 < 4; v4++) {
        *(float4*)&g_T [row*64 + ch + v4*4] = make_float4(To[v4*4],To[v4*4+1],To[v4*4+2],To[v4*4+3]);
        *(float4*)&g_vv[row*64 + ch + v4*4] = make_float4(Vo[v4*4],Vo[v4*4+1],Vo[v4*4+2],Vo[v4*4+3]);
    }
}

// ---------------- fused attention MLP: sim = relu(T@W1+b1)@W2+b2 ----------
// 64 rows per CTA; W1(64x256), W2(256x64), T-tile, hidden-tile all in SMEM.
__global__ __launch_bounds__(256, 1) void attn_mlp_kernel(
    const float* __restrict__ W1, const float* __restrict__ B1,
    const float* __restrict__ W2, const float* __restrict__ B2)
{
    extern __shared__ float sh[];
    float* w1s = sh;                         // 64*256
    float* w2s = w1s + 64*256;               // 256*64
    float* ts  = w2s + 256*64;               // 64*68
    float* hs  = ts  + 64*68;                // 64*260
    float* b1s = hs  + 64*260;               // 256
    float* b2s = b1s + 256;                  // 64
    int tid = threadIdx.x;
    int rowBase = blockIdx.x * 64;

    for (int i = tid; i < 64*256; i += 256) w1s[i] = W1[i];
    for (int i = tid; i < 256*64; i += 256) w2s[i] = W2[i];
    b1s[tid] = B1[tid];
    if (tid < 64) b2s[tid] = B2[tid];
    for (int i = tid; i < 64*64; i += 256) {
        int r = i >> 6, c = i & 63;
        ts[r*68 + c] = g_T[(rowBase + r)*64 + c];
    }
    __syncthreads();

    int rg = tid >> 4, cg = tid & 15;
    // ---- layer 1: hidden[64][256], this thread: rows rg*4..+3, cols i4*64+cg*4..+3
    float acc[4][16];
    #pragma unroll
    for (int j = 0; j < 4; j++)
        #pragma unroll
        for (int i4 = 0; i4 < 4; i4++)
            #pragma unroll
            for (int ii = 0; ii < 4; ii++)
                acc[j][i4*4+ii] = b1s[i4*64 + cg*4 + ii];

    #pragma unroll 2
    for (int k = 0; k < 64; k++) {
        float a[4];
        #pragma unroll
        for (int j = 0; j < 4; j++) a[j] = ts[(rg*4 + j)*68 + k];
        #pragma unroll
        for (int i4 = 0; i4 < 4; i4++) {
            float4 w = *(const float4*)&w1s[k*256 + i4*64 + cg*4];
            #pragma unroll
            for (int j = 0; j < 4; j++) {
                acc[j][i4*4+0] += a[j]*w.x;
                acc[j][i4*4+1] += a[j]*w.y;
                acc[j][i4*4+2] += a[j]*w.z;
                acc[j][i4*4+3] += a[j]*w.w;
            }
        }
    }
    #pragma unroll
    for (int j = 0; j < 4; j++)
        #pragma unroll
        for (int i4 = 0; i4 < 4; i4++) {
            float4 v = make_float4(fmaxf(acc[j][i4*4+0], 0.f),
                                   fmaxf(acc[j][i4*4+1], 0.f),
                                   fmaxf(acc[j][i4*4+2], 0.f),
                                   fmaxf(acc[j][i4*4+3], 0.f));
            *(float4*)&hs[(rg*4 + j)*260 + i4*64 + cg*4] = v;
        }
    __syncthreads();

    // ---- layer 2: sim[64][64], this thread: rows rg*4..+3, cols cg*4..+3
    float acc2[4][4];
    #pragma unroll
    for (int j = 0; j < 4; j++)
        #pragma unroll
        for (int i = 0; i < 4; i++)
            acc2[j][i] = b2s[cg*4 + i];

    #pragma unroll 2
    for (int k = 0; k < 256; k++) {
        float hh[4];
        #pragma unroll
        for (int j = 0; j < 4; j++) hh[j] = hs[(rg*4 + j)*260 + k];
        float4 w = *(const float4*)&w2s[k*64 + cg*4];
        #pragma unroll
        for (int j = 0; j < 4; j++) {
            acc2[j][0] += hh[j]*w.x;
            acc2[j][1] += hh[j]*w.y;
            acc2[j][2] += hh[j]*w.z;
            acc2[j][3] += hh[j]*w.w;
        }
    }
    #pragma unroll
    for (int j = 0; j < 4; j++)
        *(float4*)&g_sim[(rowBase + rg*4 + j)*64 + cg*4] =
            make_float4(acc2[j][0], acc2[j][1], acc2[j][2], acc2[j][3]);
}

// ---------------- softmax over 16 neighbors + weighted aggregation --------
__global__ void softmax_agg_kernel()
{
    int g = blockIdx.x * 256 + threadIdx.x;   // 16384*64
    int q = g >> 6, c = g & 63;
    float s[16];
    float mx = -FLT_MAX;
    #pragma unroll
    for (int j = 0; j < 16; j++) {
        s[j] = g_sim[(q*16 + j)*64 + c];
        mx = fmaxf(mx, s[j]);
    }
    float sum = 0.f;
    #pragma unroll
    for (int j = 0; j < 16; j++) {
        s[j] = __expf(s[j] - mx);
        sum += s[j];
    }
    float inv = 1.f / sum;
    float a = 0.f;
    #pragma unroll
    for (int j = 0; j < 16; j++)
        a += s[j] * g_vv[(q*16 + j)*64 + c];
    g_agg[q*64 + c] = a * inv;
}

// ---------------- copy p into output tail ---------------------------------
__global__ void finalize_p_kernel(const float* __restrict__ p, float* __restrict__ out)
{
    int i = blockIdx.x * 256 + threadIdx.x;
    out[i] = p[i];
}

// ---------------- launch ---------------------------------------------------
extern "C" void kernel_launch(void* const* d_in, const int* in_sizes, int n_in,
                              void* d_out, int out_size)
{
    const float* x      = (const float*)d_in[0];
    const float* p      = (const float*)d_in[1];
    const float* fc1_w  = (const float*)d_in[2];
    const float* fc1_b  = (const float*)d_in[3];
    const float* bn1_g  = (const float*)d_in[4];
    const float* bn1_b  = (const float*)d_in[5];
    const float* qkv_w  = (const float*)d_in[6];
    const float* pos_w1 = (const float*)d_in[7];
    const float* pos_b1 = (const float*)d_in[8];
    const float* pos_w2 = (const float*)d_in[9];
    const float* pos_b2 = (const float*)d_in[10];
    const float* attn_w1= (const float*)d_in[11];
    const float* attn_b1= (const float*)d_in[12];
    const float* attn_w2= (const float*)d_in[13];
    const float* attn_b2= (const float*)d_in[14];
    const float* bn2_g  = (const float*)d_in[15];
    const float* bn2_b  = (const float*)d_in[16];
    const float* fc2_w  = (const float*)d_in[17];
    const float* fc2_b  = (const float*)d_in[18];
    const float* bn3_g  = (const float*)d_in[19];
    const float* bn3_b  = (const float*)d_in[20];
    float* out = (float*)d_out;

    float *hpre, *h, *qkv, *agg, *u, *ypre;
    cudaGetSymbolAddress((void**)&hpre, g_hpre);
    cudaGetSymbolAddress((void**)&h,    g_h);
    cudaGetSymbolAddress((void**)&qkv,  g_qkv);
    cudaGetSymbolAddress((void**)&agg,  g_agg);
    cudaGetSymbolAddress((void**)&u,    g_u);
    cudaGetSymbolAddress((void**)&ypre, g_ypre);

    cudaFuncSetAttribute(knn_kernel, cudaFuncAttributeMaxDynamicSharedMemorySize, 81920);
    cudaFuncSetAttribute(attn_mlp_kernel, cudaFuncAttributeMaxDynamicSharedMemorySize, 216320);

    // fc1 -> bn1 -> relu (h = residual)
    gemm64_kernel<<<dim3(256,1), 256>>>(x, fc1_w, fc1_b, hpre, 64);
    bn_stats_kernel<<<64, 256>>>(hpre);
    bn_apply_kernel<<<4096, 256>>>(hpre, nullptr, bn1_g, bn1_b, h);

    // qkv projection (no bias)
    gemm64_kernel<<<dim3(256,3), 256>>>(h, qkv_w, nullptr, qkv, 192);

    // KNN (per batch)
    knn_kernel<<<dim3(128,4), 256, 81920>>>(p);

    // pe-MLP + T/vv
    build_t_kernel<<<4096, 256>>>(p, pos_w1, pos_b1, pos_w2, pos_b2);

    // fused attention MLP -> sim
    attn_mlp_kernel<<<4096, 256, 216320>>>(attn_w1, attn_b1, attn_w2, attn_b2);

    // softmax over neighbors + aggregate
    softmax_agg_kernel<<<4096, 256>>>();

    // bn2 -> relu -> + residual
    bn_stats_kernel<<<64, 256>>>(agg);
    bn_apply_kernel<<<4096, 256>>>(agg, h, bn2_g, bn2_b, u);

    // fc2 -> bn3 -> relu -> output
    gemm64_kernel<<<dim3(256,1), 256>>>(u, fc2_w, fc2_b, ypre, 64);
    bn_stats_kernel<<<64, 256>>>(ypre);
    bn_apply_kernel<<<4096, 256>>>(ypre, nullptr, bn3_g, bn3_b, out);

    // output tail: p passthrough
    finalize_p_kernel<<<192, 256>>>(p, out + NROWS*64);
}

// round 2
// speedup vs baseline: 1.5727x; 1.5727x over previous
#include <cuda_runtime.h>
#include <math.h>
#include <float.h>

#define NROWS 16384      // B*N
#define NPTS  4096
#define KNN   16
#define RTOT  (NROWS*KNN)   // 262144

// ---------------- scratch (static device allocations) ----------------
__device__ float g_hpre[NROWS*64];
__device__ float g_h[NROWS*64];       // post-bn1 relu (= residual)
__device__ float g_qkv[NROWS*192];
__device__ int   g_idx[NROWS*KNN];
__device__ float g_T[RTOT*64];
__device__ float g_vv[RTOT*64];
__device__ float g_agg[NROWS*64];
__device__ float g_u[NROWS*64];
__device__ float g_ypre[NROWS*64];
__device__ float g_mu[64];
__device__ float g_rs[64];

// ---------------- helpers ---------------------------------------------------
__device__ __forceinline__ float tf32r(float f) {
    unsigned r;
    asm("cvt.rna.tf32.f32 %0, %1;" : "=r"(r) : "f"(f));
    return __uint_as_float(r);
}

__device__ __forceinline__ void mma_tf32(float (&d)[4], const unsigned (&a)[4],
                                         unsigned b0, unsigned b1) {
    asm volatile(
        "mma.sync.aligned.m16n8k8.row.col.f32.tf32.tf32.f32 "
        "{%0,%1,%2,%3}, {%4,%5,%6,%7}, {%8,%9}, {%0,%1,%2,%3};"
        : "+f"(d[0]), "+f"(d[1]), "+f"(d[2]), "+f"(d[3])
        : "r"(a[0]), "r"(a[1]), "r"(a[2]), "r"(a[3]), "r"(b0), "r"(b1));
}

// ---------------- generic 64-K GEMM: C[R,NC] = A[R,64] @ W[64,NC] (+bias) ----
__global__ __launch_bounds__(256) void gemm64_kernel(
    const float* __restrict__ A, const float* __restrict__ W,
    const float* __restrict__ bias, float* __restrict__ Cout, int NC)
{
    __shared__ float As[64*68];
    __shared__ float Ws[64*68];
    int tid = threadIdx.x;
    int rowBase = blockIdx.x * 64;
    int colBase = blockIdx.y * 64;
    for (int i = tid; i < 4096; i += 256) {
        int r = i >> 6, c = i & 63;
        As[r*68 + c] = A[(rowBase + r)*64 + c];
        Ws[r*68 + c] = W[r*NC + colBase + c];
    }
    __syncthreads();
    int rg = tid >> 4, cg = tid & 15;
    float acc[4][4];
    #pragma unroll
    for (int j = 0; j < 4; j++)
        #pragma unroll
        for (int i = 0; i < 4; i++) acc[j][i] = 0.f;
    #pragma unroll 4
    for (int k = 0; k < 64; k++) {
        float a[4];
        #pragma unroll
        for (int j = 0; j < 4; j++) a[j] = As[(rg*4 + j)*68 + k];
        float4 w = *(const float4*)&Ws[k*68 + cg*4];
        #pragma unroll
        for (int j = 0; j < 4; j++) {
            acc[j][0] += a[j]*w.x;
            acc[j][1] += a[j]*w.y;
            acc[j][2] += a[j]*w.z;
            acc[j][3] += a[j]*w.w;
        }
    }
    #pragma unroll
    for (int j = 0; j < 4; j++) {
        int r = rowBase + rg*4 + j;
        #pragma unroll
        for (int i = 0; i < 4; i++) {
            float v = acc[j][i];
            if (bias) v += bias[colBase + cg*4 + i];
            Cout[r*NC + colBase + cg*4 + i] = v;
        }
    }
}

// ---------------- BN stats: one block per channel (deterministic) ----------
__global__ void bn_stats_kernel(const float* __restrict__ src)
{
    int c = blockIdx.x;
    float s1 = 0.f, s2 = 0.f;
    for (int r = threadIdx.x; r < NROWS; r += 256) {
        float v = src[r*64 + c];
        s1 += v; s2 += v*v;
    }
    __shared__ float sh1[256], sh2[256];
    sh1[threadIdx.x] = s1; sh2[threadIdx.x] = s2;
    __syncthreads();
    for (int st = 128; st > 0; st >>= 1) {
        if (threadIdx.x < st) {
            sh1[threadIdx.x] += sh1[threadIdx.x + st];
            sh2[threadIdx.x] += sh2[threadIdx.x + st];
        }
        __syncthreads();
    }
    if (threadIdx.x == 0) {
        float m = sh1[0] / (float)NROWS;
        float var = sh2[0] / (float)NROWS - m*m;
        g_mu[c] = m;
        g_rs[c] = rsqrtf(var + 1e-5f);
    }
}

// ---------------- BN apply + relu (+ optional residual add) ----------------
__global__ void bn_apply_kernel(const float* __restrict__ src,
                                const float* __restrict__ addsrc,
                                const float* __restrict__ gam,
                                const float* __restrict__ bet,
                                float* __restrict__ dst)
{
    int i = blockIdx.x * 256 + threadIdx.x;
    int c = i & 63;
    float v = (src[i] - g_mu[c]) * g_rs[c] * gam[c] + bet[c];
    v = fmaxf(v, 0.f);
    if (addsrc) v += addsrc[i];
    dst[i] = v;
}

// ---------------- brute-force KNN (per-warp query, SMEM point cloud) -------
__global__ __launch_bounds__(256) void knn_kernel(const float* __restrict__ p)
{
    int b = blockIdx.y;
    extern __shared__ float sh[];
    float* px = sh;
    float* py = sh + NPTS;
    float* pz = sh + 2*NPTS;
    float* sd = sh + 3*NPTS;           // 8 warps * 512 floats
    int*   si = (int*)(sd + 8*512);    // 8 warps * 512 ints
    const float* pb = p + b*NPTS*3;
    for (int i = threadIdx.x; i < NPTS; i += 256) {
        px[i] = pb[3*i];
        py[i] = pb[3*i + 1];
        pz[i] = pb[3*i + 2];
    }
    __syncthreads();
    int w = threadIdx.x >> 5, lane = threadIdx.x & 31;
    float* wd = sd + w*512;
    int*   wi = si + w*512;

    for (int qq = 0; qq < 4; qq++) {
        int n = blockIdx.x*32 + w*4 + qq;
        float qx = px[n], qy = py[n], qz = pz[n];
        float dk[16]; int ik[16];
        #pragma unroll
        for (int t = 0; t < 16; t++) { dk[t] = FLT_MAX; ik[t] = 0; }
        for (int m = lane; m < NPTS; m += 32) {
            float dx = px[m]-qx, dy = py[m]-qy, dz = pz[m]-qz;
            float d = dx*dx + dy*dy + dz*dz;
            if (d < dk[15]) {
                dk[15] = d; ik[15] = m;
                #pragma unroll
                for (int s = 15; s > 0; --s) {
                    if (dk[s] < dk[s-1]) {
                        float td = dk[s]; dk[s] = dk[s-1]; dk[s-1] = td;
                        int   ti = ik[s]; ik[s] = ik[s-1]; ik[s-1] = ti;
                    }
                }
            }
        }
        #pragma unroll
        for (int t = 0; t < 16; t++) {
            wd[lane*16 + t] = dk[t];
            wi[lane*16 + t] = ik[t];
        }
        __syncwarp();
        // merge 32 sorted lists of 16 -> global top-16
        int pos = 0;
        for (int t = 0; t < 16; t++) {
            float h = (pos < 16) ? wd[lane*16 + pos] : FLT_MAX;
            float v = h; int src = lane;
            #pragma unroll
            for (int off = 16; off > 0; off >>= 1) {
                float v2 = __shfl_down_sync(0xffffffffu, v, off);
                int   s2 = __shfl_down_sync(0xffffffffu, src, off);
                if (v2 < v || (v2 == v && s2 < src)) { v = v2; src = s2; }
            }
            src = __shfl_sync(0xffffffffu, src, 0);
            int wpos = __shfl_sync(0xffffffffu, pos, src);
            if (lane == 0) g_idx[((long)b*NPTS + n)*16 + t] = wi[src*16 + wpos];
            if (lane == src) pos++;
        }
        __syncwarp();
    }
}

// ---------------- pe-MLP + build T = q - k_j + pe, vv = v_j + pe -----------
__global__ __launch_bounds__(256) void build_t_kernel(
    const float* __restrict__ p,
    const float* __restrict__ w1, const float* __restrict__ b1,
    const float* __restrict__ w2, const float* __restrict__ b2)
{
    __shared__ float sw1[96], sb1[32], sw2[2048], sb2[64];
    int tid = threadIdx.x;
    if (tid < 96) sw1[tid] = w1[tid];
    if (tid < 32) sb1[tid] = b1[tid];
    for (int i = tid; i < 2048; i += 256) sw2[i] = w2[i];
    if (tid < 64) sb2[tid] = b2[tid];
    __syncthreads();

    int rid = tid >> 2, ch = (tid & 3) * 16;
    int row = blockIdx.x * 64 + rid;       // (b,n,j) flattened
    int q = row >> 4;                      // b*4096+n
    int b = q >> 12;
    int nb = (b << 12) + g_idx[row];       // b*4096 + neighbor

    float rx = p[q*3+0] - p[nb*3+0];
    float ry = p[q*3+1] - p[nb*3+1];
    float rz = p[q*3+2] - p[nb*3+2];

    float hid[32];
    #pragma unroll
    for (int h = 0; h < 32; h++) {
        float t = rx*sw1[h] + ry*sw1[32+h] + rz*sw1[64+h] + sb1[h];
        hid[h] = fmaxf(t, 0.f);
    }

    float qvf[16], kjf[16], vjf[16];
    #pragma unroll
    for (int v4 = 0; v4 < 4; v4++) {
        float4 t1 = *(const float4*)&g_qkv[q*192 + ch + v4*4];
        float4 t2 = *(const float4*)&g_qkv[nb*192 + 64 + ch + v4*4];
        float4 t3 = *(const float4*)&g_qkv[nb*192 + 128 + ch + v4*4];
        qvf[v4*4+0]=t1.x; qvf[v4*4+1]=t1.y; qvf[v4*4+2]=t1.z; qvf[v4*4+3]=t1.w;
        kjf[v4*4+0]=t2.x; kjf[v4*4+1]=t2.y; kjf[v4*4+2]=t2.z; kjf[v4*4+3]=t2.w;
        vjf[v4*4+0]=t3.x; vjf[v4*4+1]=t3.y; vjf[v4*4+2]=t3.z; vjf[v4*4+3]=t3.w;
    }

    float To[16], Vo[16];
    #pragma unroll
    for (int cc = 0; cc < 16; cc++) {
        float pe = sb2[ch + cc];
        #pragma unroll
        for (int h = 0; h < 32; h++) pe += hid[h] * sw2[h*64 + ch + cc];
        To[cc] = qvf[cc] - kjf[cc] + pe;
        Vo[cc] = vjf[cc] + pe;
    }
    #pragma unroll
    for (int v4 = 0; v4 < 4; v4++) {
        *(float4*)&g_T [row*64 + ch + v4*4] = make_float4(To[v4*4],To[v4*4+1],To[v4*4+2],To[v4*4+3]);
        *(float4*)&g_vv[row*64 + ch + v4*4] = make_float4(Vo[v4*4],Vo[v4*4+1],Vo[v4*4+2],Vo[v4*4+3]);
    }
}

// ---------------- fused attention MLP (tf32 tensor cores) + softmax + agg --
// Per 64-row tile (= 4 queries x 16 neighbors):
//   H[64,256] = relu(T @ W1 + b1)   (layer1, mma tf32)
//   sim[64,64] = H @ W2 + b2        (layer2, mma tf32, stays in registers)
//   softmax over the 16 rows of each query (in-warp shuffles), agg with vv.
// SMEM float offsets:
#define W1S_OFF 0              // 64 x 264  (stride 264 : %32==8, B-frag conflict-free)
#define W2T_OFF 16896          // 64 x 260  transposed [n][k] (stride %32==4)
#define TS_OFF  (16896+16640)  // 64 x 68   (stride %32==4, A-frag conflict-free)
#define HS_OFF  (TS_OFF+4352)  // 64 x 260  (stride %32==4)
#define B1S_OFF (HS_OFF+16640)
#define B2S_OFF (B1S_OFF+256)
#define ATTN_SMEM ((B2S_OFF+64)*4)

__global__ __launch_bounds__(256, 1) void attn_fused_kernel(
    const float* __restrict__ W1, const float* __restrict__ B1,
    const float* __restrict__ W2, const float* __restrict__ B2,
    int tilesPerCta)
{
    extern __shared__ float sh[];
    float* w1s = sh + W1S_OFF;
    float* w2t = sh + W2T_OFF;
    float* ts  = sh + TS_OFF;
    float* hs  = sh + HS_OFF;
    float* b1s = sh + B1S_OFF;
    float* b2s = sh + B2S_OFF;
    int tid = threadIdx.x;

    // one-time weight load (tf32-rounded)
    for (int i = tid; i < 64*256; i += 256) {
        int k = i >> 8, n = i & 255;
        w1s[k*264 + n] = tf32r(W1[i]);
    }
    for (int i = tid; i < 256*64; i += 256) {
        int k = i >> 6, n = i & 63;
        w2t[n*260 + k] = tf32r(W2[i]);
    }
    b1s[tid] = B1[tid];
    if (tid < 64) b2s[tid] = B2[tid];

    int lane = tid & 31, w = tid >> 5;
    int gid = lane >> 2, tig = lane & 3;
    // layer1 mapping: 2 warp-rows x 4 warp-cols
    int mPair  = w & 1;        // 2 m-tiles (32 rows)
    int nGroup = w >> 1;       // 64 cols
    // layer2 mapping: 4 warp-rows x 2 warp-cols
    int mt2    = w & 3;        // 1 m-tile (16 rows = one query)
    int nHalf  = w >> 2;       // 32 cols

    for (int t = 0; t < tilesPerCta; t++) {
        int rowBase = (blockIdx.x * tilesPerCta + t) * 64;
        __syncthreads();
        // load T tile (tf32-rounded)
        for (int i = tid; i < 1024; i += 256) {
            int r = i >> 4, c4 = (i & 15) * 4;
            float4 v = *(const float4*)&g_T[(rowBase + r)*64 + c4];
            float4 o = make_float4(tf32r(v.x), tf32r(v.y), tf32r(v.z), tf32r(v.w));
            *(float4*)&ts[r*68 + c4] = o;
        }
        __syncthreads();

        // ---------- layer 1: H = relu(T @ W1 + b1) ----------
        float acc1[2][8][4];
        #pragma unroll
        for (int mt = 0; mt < 2; mt++)
            #pragma unroll
            for (int nt = 0; nt < 8; nt++) {
                int colE = nGroup*64 + nt*8 + 2*tig;
                float be = b1s[colE], bo = b1s[colE + 1];
                acc1[mt][nt][0] = be; acc1[mt][nt][1] = bo;
                acc1[mt][nt][2] = be; acc1[mt][nt][3] = bo;
            }
        #pragma unroll
        for (int kb = 0; kb < 8; kb++) {
            int k0 = kb * 8;
            unsigned a[2][4];
            #pragma unroll
            for (int mt = 0; mt < 2; mt++) {
                int rb = mPair*32 + mt*16;
                a[mt][0] = __float_as_uint(ts[(rb + gid    )*68 + k0 + tig    ]);
                a[mt][1] = __float_as_uint(ts[(rb + gid + 8)*68 + k0 + tig    ]);
                a[mt][2] = __float_as_uint(ts[(rb + gid    )*68 + k0 + tig + 4]);
                a[mt][3] = __float_as_uint(ts[(rb + gid + 8)*68 + k0 + tig + 4]);
            }
            #pragma unroll
            for (int nt = 0; nt < 8; nt++) {
                int nb = nGroup*64 + nt*8;
                unsigned b0 = __float_as_uint(w1s[(k0 + tig    )*264 + nb + gid]);
                unsigned b1 = __float_as_uint(w1s[(k0 + tig + 4)*264 + nb + gid]);
                mma_tf32(acc1[0][nt], a[0], b0, b1);
                mma_tf32(acc1[1][nt], a[1], b0, b1);
            }
        }
        // relu + tf32 + store H
        #pragma unroll
        for (int mt = 0; mt < 2; mt++) {
            int rb = mPair*32 + mt*16;
            #pragma unroll
            for (int nt = 0; nt < 8; nt++) {
                int colE = nGroup*64 + nt*8 + 2*tig;
                float2 lo = make_float2(tf32r(fmaxf(acc1[mt][nt][0], 0.f)),
                                        tf32r(fmaxf(acc1[mt][nt][1], 0.f)));
                float2 hi = make_float2(tf32r(fmaxf(acc1[mt][nt][2], 0.f)),
                                        tf32r(fmaxf(acc1[mt][nt][3], 0.f)));
                *(float2*)&hs[(rb + gid    )*260 + colE] = lo;
                *(float2*)&hs[(rb + gid + 8)*260 + colE] = hi;
            }
        }
        __syncthreads();

        // ---------- layer 2: sim = H @ W2 + b2 (registers only) ----------
        float acc2[4][4];
        #pragma unroll
        for (int nt = 0; nt < 4; nt++) {
            int colE = nHalf*32 + nt*8 + 2*tig;
            float be = b2s[colE], bo = b2s[colE + 1];
            acc2[nt][0] = be; acc2[nt][1] = bo;
            acc2[nt][2] = be; acc2[nt][3] = bo;
        }
        int rb2 = mt2 * 16;
        #pragma unroll 4
        for (int kb = 0; kb < 32; kb++) {
            int k0 = kb * 8;
            unsigned a[4];
            a[0] = __float_as_uint(hs[(rb2 + gid    )*260 + k0 + tig    ]);
            a[1] = __float_as_uint(hs[(rb2 + gid + 8)*260 + k0 + tig    ]);
            a[2] = __float_as_uint(hs[(rb2 + gid    )*260 + k0 + tig + 4]);
            a[3] = __float_as_uint(hs[(rb2 + gid + 8)*260 + k0 + tig + 4]);
            #pragma unroll
            for (int nt = 0; nt < 4; nt++) {
                int nb = nHalf*32 + nt*8;
                unsigned b0 = __float_as_uint(w2t[(nb + gid)*260 + k0 + tig    ]);
                unsigned b1 = __float_as_uint(w2t[(nb + gid)*260 + k0 + tig + 4]);
                mma_tf32(acc2[nt], a, b0, b1);
            }
        }

        // ---------- softmax over the 16 rows of this query + agg ----------
        // acc2[nt][0]: (row gid,   col 2tig) ; [1]: col 2tig+1
        // acc2[nt][2]: (row gid+8, col 2tig) ; [3]: col 2tig+1
        int qrow = rowBase + mt2*16;
        int qout = (rowBase >> 4) + mt2;
        #pragma unroll
        for (int nt = 0; nt < 4; nt++) {
            int colE = nHalf*32 + nt*8 + 2*tig;
            float me = fmaxf(acc2[nt][0], acc2[nt][2]);
            float mo = fmaxf(acc2[nt][1], acc2[nt][3]);
            #pragma unroll
            for (int off = 4; off < 32; off <<= 1) {
                me = fmaxf(me, __shfl_xor_sync(0xffffffffu, me, off));
                mo = fmaxf(mo, __shfl_xor_sync(0xffffffffu, mo, off));
            }
            float e0 = __expf(acc2[nt][0] - me);
            float e1 = __expf(acc2[nt][1] - mo);
            float e2 = __expf(acc2[nt][2] - me);
            float e3 = __expf(acc2[nt][3] - mo);

            float2 v0 = *(const float2*)&g_vv[(qrow + gid    )*64 + colE];
            float2 v1 = *(const float2*)&g_vv[(qrow + gid + 8)*64 + colE];

            float se = e0 + e2;
            float so = e1 + e3;
            float pe = e0*v0.x + e2*v1.x;
            float po = e1*v0.y + e3*v1.y;
            #pragma unroll
            for (int off = 4; off < 32; off <<= 1) {
                se += __shfl_xor_sync(0xffffffffu, se, off);
                so += __shfl_xor_sync(0xffffffffu, so, off);
                pe += __shfl_xor_sync(0xffffffffu, pe, off);
                po += __shfl_xor_sync(0xffffffffu, po, off);
            }
            if (gid == 0) {
                float2 outv = make_float2(pe / se, po / so);
                *(float2*)&g_agg[qout*64 + colE] = outv;
            }
        }
    }
}

// ---------------- copy p into output tail ---------------------------------
__global__ void finalize_p_kernel(const float* __restrict__ p, float* __restrict__ out)
{
    int i = blockIdx.x * 256 + threadIdx.x;
    out[i] = p[i];
}

// ---------------- launch ---------------------------------------------------
extern "C" void kernel_launch(void* const* d_in, const int* in_sizes, int n_in,
                              void* d_out, int out_size)
{
    const float* x      = (const float*)d_in[0];
    const float* p      = (const float*)d_in[1];
    const float* fc1_w  = (const float*)d_in[2];
    const float* fc1_b  = (const float*)d_in[3];
    const float* bn1_g  = (const float*)d_in[4];
    const float* bn1_b  = (const float*)d_in[5];
    const float* qkv_w  = (const float*)d_in[6];
    const float* pos_w1 = (const float*)d_in[7];
    const float* pos_b1 = (const float*)d_in[8];
    const float* pos_w2 = (const float*)d_in[9];
    const float* pos_b2 = (const float*)d_in[10];
    const float* attn_w1= (const float*)d_in[11];
    const float* attn_b1= (const float*)d_in[12];
    const float* attn_w2= (const float*)d_in[13];
    const float* attn_b2= (const float*)d_in[14];
    const float* bn2_g  = (const float*)d_in[15];
    const float* bn2_b  = (const float*)d_in[16];
    const float* fc2_w  = (const float*)d_in[17];
    const float* fc2_b  = (const float*)d_in[18];
    const float* bn3_g  = (const float*)d_in[19];
    const float* bn3_b  = (const float*)d_in[20];
    float* out = (float*)d_out;

    float *hpre, *h, *qkv, *agg, *u, *ypre;
    cudaGetSymbolAddress((void**)&hpre, g_hpre);
    cudaGetSymbolAddress((void**)&h,    g_h);
    cudaGetSymbolAddress((void**)&qkv,  g_qkv);
    cudaGetSymbolAddress((void**)&agg,  g_agg);
    cudaGetSymbolAddress((void**)&u,    g_u);
    cudaGetSymbolAddress((void**)&ypre, g_ypre);

    cudaFuncSetAttribute(knn_kernel, cudaFuncAttributeMaxDynamicSharedMemorySize, 81920);
    cudaFuncSetAttribute(attn_fused_kernel, cudaFuncAttributeMaxDynamicSharedMemorySize, ATTN_SMEM);

    // fc1 -> bn1 -> relu (h = residual)
    gemm64_kernel<<<dim3(256,1), 256>>>(x, fc1_w, fc1_b, hpre, 64);
    bn_stats_kernel<<<64, 256>>>(hpre);
    bn_apply_kernel<<<4096, 256>>>(hpre, nullptr, bn1_g, bn1_b, h);

    // qkv projection (no bias)
    gemm64_kernel<<<dim3(256,3), 256>>>(h, qkv_w, nullptr, qkv, 192);

    // KNN (per batch)
    knn_kernel<<<dim3(128,4), 256, 81920>>>(p);

    // pe-MLP + T/vv
    build_t_kernel<<<4096, 256>>>(p, pos_w1, pos_b1, pos_w2, pos_b2);

    // fused attention MLP (tf32 mma) + softmax + aggregation
    attn_fused_kernel<<<1024, 256, ATTN_SMEM>>>(attn_w1, attn_b1, attn_w2, attn_b2, 4);

    // bn2 -> relu -> + residual
    bn_stats_kernel<<<64, 256>>>(agg);
    bn_apply_kernel<<<4096, 256>>>(agg, h, bn2_g, bn2_b, u);

    // fc2 -> bn3 -> relu -> output
    gemm64_kernel<<<dim3(256,1), 256>>>(u, fc2_w, fc2_b, ypre, 64);
    bn_stats_kernel<<<64, 256>>>(ypre);
    bn_apply_kernel<<<4096, 256>>>(ypre, nullptr, bn3_g, bn3_b, out);

    // output tail: p passthrough
    finalize_p_kernel<<<192, 256>>>(p, out + NROWS*64);
}

// round 3
// speedup vs baseline: 1.7135x; 1.0895x over previous
#include <cuda_runtime.h>
#include <math.h>
#include <float.h>

#define NROWS 16384      // B*N
#define NPTS  4096
#define KNN   16
#define RTOT  (NROWS*KNN)   // 262144

// ---------------- scratch (static device allocations) ----------------
__device__ float g_hpre[NROWS*64];
__device__ float g_h[NROWS*64];       // post-bn1 relu (= residual)
__device__ float g_qkv[NROWS*192];
__device__ int   g_idx[NROWS*KNN];
__device__ float g_T[RTOT*64];
__device__ float g_vv[RTOT*64];
__device__ float g_agg[NROWS*64];
__device__ float g_u[NROWS*64];
__device__ float g_ypre[NROWS*64];
__device__ float g_mu[64];
__device__ float g_rs[64];

// ---------------- helpers ---------------------------------------------------
__device__ __forceinline__ float tf32r(float f) {
    unsigned r;
    asm("cvt.rna.tf32.f32 %0, %1;" : "=r"(r) : "f"(f));
    return __uint_as_float(r);
}

__device__ __forceinline__ void mma_tf32(float (&d)[4], const unsigned (&a)[4],
                                         unsigned b0, unsigned b1) {
    asm volatile(
        "mma.sync.aligned.m16n8k8.row.col.f32.tf32.tf32.f32 "
        "{%0,%1,%2,%3}, {%4,%5,%6,%7}, {%8,%9}, {%0,%1,%2,%3};"
        : "+f"(d[0]), "+f"(d[1]), "+f"(d[2]), "+f"(d[3])
        : "r"(a[0]), "r"(a[1]), "r"(a[2]), "r"(a[3]), "r"(b0), "r"(b1));
}

// ---------------- tf32-mma GEMM: C[R,NC] = A[R,64] @ W[64,NC] (+bias) -------
// 64 rows per CTA, 8 warps: warp w -> m-tile (w&3), n-half (w>>2).
template<int NC>
__global__ __launch_bounds__(256) void gemm_mma_kernel(
    const float* __restrict__ A, const float* __restrict__ W,
    const float* __restrict__ bias, float* __restrict__ Cout)
{
    constexpr int NHALF  = NC / 2;
    constexpr int NTILES = NHALF / 8;
    extern __shared__ float sm[];
    float* As = sm;              // 64 x 68
    float* Wt = sm + 64*68;      // NC x 68  ([n][k], stride%32==4)
    int tid = threadIdx.x;
    int rowBase = blockIdx.x * 64;

    for (int i = tid; i < 64*64; i += 256) {
        int r = i >> 6, c = i & 63;
        As[r*68 + c] = tf32r(A[(rowBase + r)*64 + c]);
    }
    for (int i = tid; i < 64*NC; i += 256) {
        int k = i / NC, n = i % NC;
        Wt[n*68 + k] = tf32r(W[i]);
    }
    __syncthreads();

    int lane = tid & 31, w = tid >> 5;
    int gid = lane >> 2, tig = lane & 3;
    int mt = w & 3, nHalf = w >> 2;
    int rb = mt * 16;

    float acc[NTILES][4];
    #pragma unroll
    for (int nt = 0; nt < NTILES; nt++) {
        int colE = nHalf*NHALF + nt*8 + 2*tig;
        float be = bias ? bias[colE]   : 0.f;
        float bo = bias ? bias[colE+1] : 0.f;
        acc[nt][0] = be; acc[nt][1] = bo;
        acc[nt][2] = be; acc[nt][3] = bo;
    }
    #pragma unroll
    for (int kb = 0; kb < 8; kb++) {
        int k0 = kb * 8;
        unsigned a[4];
        a[0] = __float_as_uint(As[(rb + gid    )*68 + k0 + tig    ]);
        a[1] = __float_as_uint(As[(rb + gid + 8)*68 + k0 + tig    ]);
        a[2] = __float_as_uint(As[(rb + gid    )*68 + k0 + tig + 4]);
        a[3] = __float_as_uint(As[(rb + gid + 8)*68 + k0 + tig + 4]);
        #pragma unroll
        for (int nt = 0; nt < NTILES; nt++) {
            int nb = nHalf*NHALF + nt*8;
            unsigned b0 = __float_as_uint(Wt[(nb + gid)*68 + k0 + tig    ]);
            unsigned b1 = __float_as_uint(Wt[(nb + gid)*68 + k0 + tig + 4]);
            mma_tf32(acc[nt], a, b0, b1);
        }
    }
    #pragma unroll
    for (int nt = 0; nt < NTILES; nt++) {
        int colE = nHalf*NHALF + nt*8 + 2*tig;
        *(float2*)&Cout[(rowBase + rb + gid    )*NC + colE] = make_float2(acc[nt][0], acc[nt][1]);
        *(float2*)&Cout[(rowBase + rb + gid + 8)*NC + colE] = make_float2(acc[nt][2], acc[nt][3]);
    }
}

// ---------------- BN stats: one block per channel (deterministic) ----------
__global__ void bn_stats_kernel(const float* __restrict__ src)
{
    int c = blockIdx.x;
    float s1 = 0.f, s2 = 0.f;
    for (int r = threadIdx.x; r < NROWS; r += 256) {
        float v = src[r*64 + c];
        s1 += v; s2 += v*v;
    }
    __shared__ float sh1[256], sh2[256];
    sh1[threadIdx.x] = s1; sh2[threadIdx.x] = s2;
    __syncthreads();
    for (int st = 128; st > 0; st >>= 1) {
        if (threadIdx.x < st) {
            sh1[threadIdx.x] += sh1[threadIdx.x + st];
            sh2[threadIdx.x] += sh2[threadIdx.x + st];
        }
        __syncthreads();
    }
    if (threadIdx.x == 0) {
        float m = sh1[0] / (float)NROWS;
        float var = sh2[0] / (float)NROWS - m*m;
        g_mu[c] = m;
        g_rs[c] = rsqrtf(var + 1e-5f);
    }
}

// ---------------- BN apply + relu (+ optional residual add) ----------------
__global__ void bn_apply_kernel(const float* __restrict__ src,
                                const float* __restrict__ addsrc,
                                const float* __restrict__ gam,
                                const float* __restrict__ bet,
                                float* __restrict__ dst)
{
    int i = blockIdx.x * 256 + threadIdx.x;
    int c = i & 63;
    float v = (src[i] - g_mu[c]) * g_rs[c] * gam[c] + bet[c];
    v = fmaxf(v, 0.f);
    if (addsrc) v += addsrc[i];
    dst[i] = v;
}

// ---------------- brute-force KNN (per-warp query, SMEM point cloud) -------
__global__ __launch_bounds__(256) void knn_kernel(const float* __restrict__ p)
{
    int b = blockIdx.y;
    extern __shared__ float sh[];
    float* px = sh;
    float* py = sh + NPTS;
    float* pz = sh + 2*NPTS;
    float* sd = sh + 3*NPTS;           // 8 warps * 512 floats
    int*   si = (int*)(sd + 8*512);    // 8 warps * 512 ints
    const float* pb = p + b*NPTS*3;
    for (int i = threadIdx.x; i < NPTS; i += 256) {
        px[i] = pb[3*i];
        py[i] = pb[3*i + 1];
        pz[i] = pb[3*i + 2];
    }
    __syncthreads();
    int w = threadIdx.x >> 5, lane = threadIdx.x & 31;
    float* wd = sd + w*512;
    int*   wi = si + w*512;

    for (int qq = 0; qq < 4; qq++) {
        int n = blockIdx.x*32 + w*4 + qq;
        float qx = px[n], qy = py[n], qz = pz[n];
        float dk[16]; int ik[16];
        #pragma unroll
        for (int t = 0; t < 16; t++) { dk[t] = FLT_MAX; ik[t] = 0; }
        for (int m = lane; m < NPTS; m += 32) {
            float dx = px[m]-qx, dy = py[m]-qy, dz = pz[m]-qz;
            float d = dx*dx + dy*dy + dz*dz;
            if (d < dk[15]) {
                dk[15] = d; ik[15] = m;
                #pragma unroll
                for (int s = 15; s > 0; --s) {
                    if (dk[s] < dk[s-1]) {
                        float td = dk[s]; dk[s] = dk[s-1]; dk[s-1] = td;
                        int   ti = ik[s]; ik[s] = ik[s-1]; ik[s-1] = ti;
                    }
                }
            }
        }
        #pragma unroll
        for (int t = 0; t < 16; t++) {
            wd[lane*16 + t] = dk[t];
            wi[lane*16 + t] = ik[t];
        }
        __syncwarp();
        // merge 32 sorted lists of 16 -> global top-16
        int pos = 0;
        for (int t = 0; t < 16; t++) {
            float h = (pos < 16) ? wd[lane*16 + pos] : FLT_MAX;
            float v = h; int src = lane;
            #pragma unroll
            for (int off = 16; off > 0; off >>= 1) {
                float v2 = __shfl_down_sync(0xffffffffu, v, off);
                int   s2 = __shfl_down_sync(0xffffffffu, src, off);
                if (v2 < v || (v2 == v && s2 < src)) { v = v2; src = s2; }
            }
            src = __shfl_sync(0xffffffffu, src, 0);
            int wpos = __shfl_sync(0xffffffffu, pos, src);
            if (lane == 0) g_idx[((long)b*NPTS + n)*16 + t] = wi[src*16 + wpos];
            if (lane == src) pos++;
        }
        __syncwarp();
    }
}

// ---------------- pe-MLP (tf32 mma) + build T = q - k_j + pe, vv = v_j + pe
__global__ __launch_bounds__(256) void build_t_kernel(
    const float* __restrict__ p,
    const float* __restrict__ w1, const float* __restrict__ b1,
    const float* __restrict__ w2, const float* __restrict__ b2)
{
    __shared__ float pw1s[96], pb1s[32], pb2s[64];
    __shared__ float pw2t[64*36];   // [n][k], stride 36 (%32==4)
    __shared__ float hids[64*36];   // [row][h], stride 36
    __shared__ float pes[64*68];    // [row][c], stride 68
    int tid = threadIdx.x;
    if (tid < 96) pw1s[tid] = w1[tid];
    if (tid < 32) pb1s[tid] = b1[tid];
    if (tid < 64) pb2s[tid] = b2[tid];
    for (int i = tid; i < 2048; i += 256) {
        int k = i >> 6, n = i & 63;
        pw2t[n*36 + k] = tf32r(w2[i]);
    }
    __syncthreads();

    int rid = tid >> 2;
    int row = blockIdx.x * 64 + rid;       // (b,n,j) flattened
    int q = row >> 4;                      // b*4096+n
    int b = q >> 12;
    int nb = (b << 12) + g_idx[row];       // b*4096 + neighbor

    float rx = p[q*3+0] - p[nb*3+0];
    float ry = p[q*3+1] - p[nb*3+1];
    float rz = p[q*3+2] - p[nb*3+2];

    // hid: 4 threads per row, 8 h-values each
    {
        int h0 = (tid & 3) * 8;
        #pragma unroll
        for (int j = 0; j < 8; j++) {
            int h = h0 + j;
            float t = rx*pw1s[h] + ry*pw1s[32+h] + rz*pw1s[64+h] + pb1s[h];
            hids[rid*36 + h] = tf32r(fmaxf(t, 0.f));
        }
    }
    __syncthreads();

    // pe = relu_hid @ pos_w2 + pos_b2  (tf32 mma, K=32)
    {
        int lane = tid & 31, w = tid >> 5;
        int gid = lane >> 2, tig = lane & 3;
        int mt = w & 3, nHalf = w >> 2;
        int rb = mt * 16;
        float acc[4][4];
        #pragma unroll
        for (int nt = 0; nt < 4; nt++) {
            int colE = nHalf*32 + nt*8 + 2*tig;
            float be = pb2s[colE], bo = pb2s[colE+1];
            acc[nt][0] = be; acc[nt][1] = bo;
            acc[nt][2] = be; acc[nt][3] = bo;
        }
        #pragma unroll
        for (int kb = 0; kb < 4; kb++) {
            int k0 = kb * 8;
            unsigned a[4];
            a[0] = __float_as_uint(hids[(rb + gid    )*36 + k0 + tig    ]);
            a[1] = __float_as_uint(hids[(rb + gid + 8)*36 + k0 + tig    ]);
            a[2] = __float_as_uint(hids[(rb + gid    )*36 + k0 + tig + 4]);
            a[3] = __float_as_uint(hids[(rb + gid + 8)*36 + k0 + tig + 4]);
            #pragma unroll
            for (int nt = 0; nt < 4; nt++) {
                int nbase = nHalf*32 + nt*8;
                unsigned b0 = __float_as_uint(pw2t[(nbase + gid)*36 + k0 + tig    ]);
                unsigned b1 = __float_as_uint(pw2t[(nbase + gid)*36 + k0 + tig + 4]);
                mma_tf32(acc[nt], a, b0, b1);
            }
        }
        #pragma unroll
        for (int nt = 0; nt < 4; nt++) {
            int colE = nHalf*32 + nt*8 + 2*tig;
            *(float2*)&pes[(rb + gid    )*68 + colE] = make_float2(acc[nt][0], acc[nt][1]);
            *(float2*)&pes[(rb + gid + 8)*68 + colE] = make_float2(acc[nt][2], acc[nt][3]);
        }
    }
    __syncthreads();

    // assemble T and vv (each thread: 16 channels of its row)
    int ch = (tid & 3) * 16;
    #pragma unroll
    for (int v4 = 0; v4 < 4; v4++) {
        float4 t1 = *(const float4*)&g_qkv[q*192 + ch + v4*4];
        float4 t2 = *(const float4*)&g_qkv[nb*192 + 64 + ch + v4*4];
        float4 t3 = *(const float4*)&g_qkv[nb*192 + 128 + ch + v4*4];
        float4 pe = *(const float4*)&pes[rid*68 + ch + v4*4];
        float4 To = make_float4(t1.x - t2.x + pe.x, t1.y - t2.y + pe.y,
                                t1.z - t2.z + pe.z, t1.w - t2.w + pe.w);
        float4 Vo = make_float4(t3.x + pe.x, t3.y + pe.y,
                                t3.z + pe.z, t3.w + pe.w);
        *(float4*)&g_T [row*64 + ch + v4*4] = To;
        *(float4*)&g_vv[row*64 + ch + v4*4] = Vo;
    }
}

// ---------------- fused attention MLP (tf32 tensor cores) + softmax + agg --
#define W1S_OFF 0              // 64 x 264
#define W2T_OFF 16896          // 64 x 260 transposed [n][k]
#define TS_OFF  (16896+16640)  // 64 x 68
#define HS_OFF  (TS_OFF+4352)  // 64 x 260
#define B1S_OFF (HS_OFF+16640)
#define B2S_OFF (B1S_OFF+256)
#define ATTN_SMEM ((B2S_OFF+64)*4)

__global__ __launch_bounds__(256, 1) void attn_fused_kernel(
    const float* __restrict__ W1, const float* __restrict__ B1,
    const float* __restrict__ W2, const float* __restrict__ B2,
    int tilesPerCta)
{
    extern __shared__ float sh[];
    float* w1s = sh + W1S_OFF;
    float* w2t = sh + W2T_OFF;
    float* ts  = sh + TS_OFF;
    float* hs  = sh + HS_OFF;
    float* b1s = sh + B1S_OFF;
    float* b2s = sh + B2S_OFF;
    int tid = threadIdx.x;

    for (int i = tid; i < 64*256; i += 256) {
        int k = i >> 8, n = i & 255;
        w1s[k*264 + n] = tf32r(W1[i]);
    }
    for (int i = tid; i < 256*64; i += 256) {
        int k = i >> 6, n = i & 63;
        w2t[n*260 + k] = tf32r(W2[i]);
    }
    b1s[tid] = B1[tid];
    if (tid < 64) b2s[tid] = B2[tid];

    int lane = tid & 31, w = tid >> 5;
    int gid = lane >> 2, tig = lane & 3;
    int mPair  = w & 1;        // layer1: 2 m-tiles
    int nGroup = w >> 1;       // layer1: 64 cols
    int mt2    = w & 3;        // layer2: 1 m-tile (one query)
    int nHalf  = w >> 2;       // layer2: 32 cols

    for (int t = 0; t < tilesPerCta; t++) {
        int rowBase = (blockIdx.x * tilesPerCta + t) * 64;
        __syncthreads();
        for (int i = tid; i < 1024; i += 256) {
            int r = i >> 4, c4 = (i & 15) * 4;
            float4 v = *(const float4*)&g_T[(rowBase + r)*64 + c4];
            float4 o = make_float4(tf32r(v.x), tf32r(v.y), tf32r(v.z), tf32r(v.w));
            *(float4*)&ts[r*68 + c4] = o;
        }
        __syncthreads();

        // ---------- layer 1 ----------
        float acc1[2][8][4];
        #pragma unroll
        for (int mt = 0; mt < 2; mt++)
            #pragma unroll
            for (int nt = 0; nt < 8; nt++) {
                int colE = nGroup*64 + nt*8 + 2*tig;
                float be = b1s[colE], bo = b1s[colE + 1];
                acc1[mt][nt][0] = be; acc1[mt][nt][1] = bo;
                acc1[mt][nt][2] = be; acc1[mt][nt][3] = bo;
            }
        #pragma unroll
        for (int kb = 0; kb < 8; kb++) {
            int k0 = kb * 8;
            unsigned a[2][4];
            #pragma unroll
            for (int mt = 0; mt < 2; mt++) {
                int rb = mPair*32 + mt*16;
                a[mt][0] = __float_as_uint(ts[(rb + gid    )*68 + k0 + tig    ]);
                a[mt][1] = __float_as_uint(ts[(rb + gid + 8)*68 + k0 + tig    ]);
                a[mt][2] = __float_as_uint(ts[(rb + gid    )*68 + k0 + tig + 4]);
                a[mt][3] = __float_as_uint(ts[(rb + gid + 8)*68 + k0 + tig + 4]);
            }
            #pragma unroll
            for (int nt = 0; nt < 8; nt++) {
                int nb = nGroup*64 + nt*8;
                unsigned b0 = __float_as_uint(w1s[(k0 + tig    )*264 + nb + gid]);
                unsigned b1 = __float_as_uint(w1s[(k0 + tig + 4)*264 + nb + gid]);
                mma_tf32(acc1[0][nt], a[0], b0, b1);
                mma_tf32(acc1[1][nt], a[1], b0, b1);
            }
        }
        #pragma unroll
        for (int mt = 0; mt < 2; mt++) {
            int rb = mPair*32 + mt*16;
            #pragma unroll
            for (int nt = 0; nt < 8; nt++) {
                int colE = nGroup*64 + nt*8 + 2*tig;
                float2 lo = make_float2(tf32r(fmaxf(acc1[mt][nt][0], 0.f)),
                                        tf32r(fmaxf(acc1[mt][nt][1], 0.f)));
                float2 hi = make_float2(tf32r(fmaxf(acc1[mt][nt][2], 0.f)),
                                        tf32r(fmaxf(acc1[mt][nt][3], 0.f)));
                *(float2*)&hs[(rb + gid    )*260 + colE] = lo;
                *(float2*)&hs[(rb + gid + 8)*260 + colE] = hi;
            }
        }
        __syncthreads();

        // ---------- layer 2 ----------
        float acc2[4][4];
        #pragma unroll
        for (int nt = 0; nt < 4; nt++) {
            int colE = nHalf*32 + nt*8 + 2*tig;
            float be = b2s[colE], bo = b2s[colE + 1];
            acc2[nt][0] = be; acc2[nt][1] = bo;
            acc2[nt][2] = be; acc2[nt][3] = bo;
        }
        int rb2 = mt2 * 16;
        #pragma unroll 4
        for (int kb = 0; kb < 32; kb++) {
            int k0 = kb * 8;
            unsigned a[4];
            a[0] = __float_as_uint(hs[(rb2 + gid    )*260 + k0 + tig    ]);
            a[1] = __float_as_uint(hs[(rb2 + gid + 8)*260 + k0 + tig    ]);
            a[2] = __float_as_uint(hs[(rb2 + gid    )*260 + k0 + tig + 4]);
            a[3] = __float_as_uint(hs[(rb2 + gid + 8)*260 + k0 + tig + 4]);
            #pragma unroll
            for (int nt = 0; nt < 4; nt++) {
                int nb = nHalf*32 + nt*8;
                unsigned b0 = __float_as_uint(w2t[(nb + gid)*260 + k0 + tig    ]);
                unsigned b1 = __float_as_uint(w2t[(nb + gid)*260 + k0 + tig + 4]);
                mma_tf32(acc2[nt], a, b0, b1);
            }
        }

        // ---------- softmax over 16 neighbors + aggregation ----------
        int qrow = rowBase + mt2*16;
        int qout = (rowBase >> 4) + mt2;
        #pragma unroll
        for (int nt = 0; nt < 4; nt++) {
            int colE = nHalf*32 + nt*8 + 2*tig;
            float me = fmaxf(acc2[nt][0], acc2[nt][2]);
            float mo = fmaxf(acc2[nt][1], acc2[nt][3]);
            #pragma unroll
            for (int off = 4; off < 32; off <<= 1) {
                me = fmaxf(me, __shfl_xor_sync(0xffffffffu, me, off));
                mo = fmaxf(mo, __shfl_xor_sync(0xffffffffu, mo, off));
            }
            float e0 = __expf(acc2[nt][0] - me);
            float e1 = __expf(acc2[nt][1] - mo);
            float e2 = __expf(acc2[nt][2] - me);
            float e3 = __expf(acc2[nt][3] - mo);

            float2 v0 = *(const float2*)&g_vv[(qrow + gid    )*64 + colE];
            float2 v1 = *(const float2*)&g_vv[(qrow + gid + 8)*64 + colE];

            float se = e0 + e2;
            float so = e1 + e3;
            float pe = e0*v0.x + e2*v1.x;
            float po = e1*v0.y + e3*v1.y;
            #pragma unroll
            for (int off = 4; off < 32; off <<= 1) {
                se += __shfl_xor_sync(0xffffffffu, se, off);
                so += __shfl_xor_sync(0xffffffffu, so, off);
                pe += __shfl_xor_sync(0xffffffffu, pe, off);
                po += __shfl_xor_sync(0xffffffffu, po, off);
            }
            if (gid == 0) {
                float2 outv = make_float2(pe / se, po / so);
                *(float2*)&g_agg[qout*64 + colE] = outv;
            }
        }
    }
}

// ---------------- copy p into output tail ---------------------------------
__global__ void finalize_p_kernel(const float* __restrict__ p, float* __restrict__ out)
{
    int i = blockIdx.x * 256 + threadIdx.x;
    out[i] = p[i];
}

// ---------------- launch ---------------------------------------------------
extern "C" void kernel_launch(void* const* d_in, const int* in_sizes, int n_in,
                              void* d_out, int out_size)
{
    const float* x      = (const float*)d_in[0];
    const float* p      = (const float*)d_in[1];
    const float* fc1_w  = (const float*)d_in[2];
    const float* fc1_b  = (const float*)d_in[3];
    const float* bn1_g  = (const float*)d_in[4];
    const float* bn1_b  = (const float*)d_in[5];
    const float* qkv_w  = (const float*)d_in[6];
    const float* pos_w1 = (const float*)d_in[7];
    const float* pos_b1 = (const float*)d_in[8];
    const float* pos_w2 = (const float*)d_in[9];
    const float* pos_b2 = (const float*)d_in[10];
    const float* attn_w1= (const float*)d_in[11];
    const float* attn_b1= (const float*)d_in[12];
    const float* attn_w2= (const float*)d_in[13];
    const float* attn_b2= (const float*)d_in[14];
    const float* bn2_g  = (const float*)d_in[15];
    const float* bn2_b  = (const float*)d_in[16];
    const float* fc2_w  = (const float*)d_in[17];
    const float* fc2_b  = (const float*)d_in[18];
    const float* bn3_g  = (const float*)d_in[19];
    const float* bn3_b  = (const float*)d_in[20];
    float* out = (float*)d_out;

    float *hpre, *h, *qkv, *agg, *u, *ypre;
    cudaGetSymbolAddress((void**)&hpre, g_hpre);
    cudaGetSymbolAddress((void**)&h,    g_h);
    cudaGetSymbolAddress((void**)&qkv,  g_qkv);
    cudaGetSymbolAddress((void**)&agg,  g_agg);
    cudaGetSymbolAddress((void**)&u,    g_u);
    cudaGetSymbolAddress((void**)&ypre, g_ypre);

    const int SMEM_G64  = (64*68 + 64*68 ) * 4;   // ~35 KB
    const int SMEM_G192 = (64*68 + 192*68) * 4;   // ~70 KB
    cudaFuncSetAttribute(knn_kernel, cudaFuncAttributeMaxDynamicSharedMemorySize, 81920);
    cudaFuncSetAttribute(attn_fused_kernel, cudaFuncAttributeMaxDynamicSharedMemorySize, ATTN_SMEM);
    cudaFuncSetAttribute(gemm_mma_kernel<64>,  cudaFuncAttributeMaxDynamicSharedMemorySize, SMEM_G64);
    cudaFuncSetAttribute(gemm_mma_kernel<192>, cudaFuncAttributeMaxDynamicSharedMemorySize, SMEM_G192);

    // fc1 -> bn1 -> relu (h = residual)
    gemm_mma_kernel<64><<<256, 256, SMEM_G64>>>(x, fc1_w, fc1_b, hpre);
    bn_stats_kernel<<<64, 256>>>(hpre);
    bn_apply_kernel<<<4096, 256>>>(hpre, nullptr, bn1_g, bn1_b, h);

    // qkv projection (no bias)
    gemm_mma_kernel<192><<<256, 256, SMEM_G192>>>(h, qkv_w, nullptr, qkv);

    // KNN (per batch)
    knn_kernel<<<dim3(128,4), 256, 81920>>>(p);

    // pe-MLP (mma) + T/vv
    build_t_kernel<<<4096, 256>>>(p, pos_w1, pos_b1, pos_w2, pos_b2);

    // fused attention MLP (tf32 mma) + softmax + aggregation
    attn_fused_kernel<<<1024, 256, ATTN_SMEM>>>(attn_w1, attn_b1, attn_w2, attn_b2, 4);

    // bn2 -> relu -> + residual
    bn_stats_kernel<<<64, 256>>>(agg);
    bn_apply_kernel<<<4096, 256>>>(agg, h, bn2_g, bn2_b, u);

    // fc2 -> bn3 -> relu -> output
    gemm_mma_kernel<64><<<256, 256, SMEM_G64>>>(u, fc2_w, fc2_b, ypre);
    bn_stats_kernel<<<64, 256>>>(ypre);
    bn_apply_kernel<<<4096, 256>>>(ypre, nullptr, bn3_g, bn3_b, out);

    // output tail: p passthrough
    finalize_p_kernel<<<192, 256>>>(p, out + NROWS*64);
}

// round 4
// speedup vs baseline: 2.6632x; 1.5542x over previous
#include <cuda_runtime.h>
#include <cuda_fp16.h>
#include <math.h>
#include <float.h>

#define NROWS 16384      // B*N
#define NPTS  4096
#define KNN   16
#define RTOT  (NROWS*KNN)   // 262144

// ---------------- scratch (static device allocations) ----------------
__device__ float g_hpre[NROWS*64];
__device__ float g_h[NROWS*64];       // post-bn1 relu (= residual)
__device__ float g_qkv[NROWS*192];
__device__ int   g_idx[NROWS*KNN];
__device__ float g_T[RTOT*64];
__device__ float g_vv[RTOT*64];
__device__ float g_agg[NROWS*64];
__device__ float g_u[NROWS*64];
__device__ float g_ypre[NROWS*64];
__device__ float g_mu[64];
__device__ float g_rs[64];

// ---------------- helpers ---------------------------------------------------
__device__ __forceinline__ float tf32r(float f) {
    unsigned r;
    asm("cvt.rna.tf32.f32 %0, %1;" : "=r"(r) : "f"(f));
    return __uint_as_float(r);
}

__device__ __forceinline__ void mma_tf32(float (&d)[4], const unsigned (&a)[4],
                                         unsigned b0, unsigned b1) {
    asm volatile(
        "mma.sync.aligned.m16n8k8.row.col.f32.tf32.tf32.f32 "
        "{%0,%1,%2,%3}, {%4,%5,%6,%7}, {%8,%9}, {%0,%1,%2,%3};"
        : "+f"(d[0]), "+f"(d[1]), "+f"(d[2]), "+f"(d[3])
        : "r"(a[0]), "r"(a[1]), "r"(a[2]), "r"(a[3]), "r"(b0), "r"(b1));
}

__device__ __forceinline__ void mma_f16(float (&d)[4], const unsigned (&a)[4],
                                        unsigned b0, unsigned b1) {
    asm volatile(
        "mma.sync.aligned.m16n8k16.row.col.f32.f16.f16.f32 "
        "{%0,%1,%2,%3}, {%4,%5,%6,%7}, {%8,%9}, {%0,%1,%2,%3};"
        : "+f"(d[0]), "+f"(d[1]), "+f"(d[2]), "+f"(d[3])
        : "r"(a[0]), "r"(a[1]), "r"(a[2]), "r"(a[3]), "r"(b0), "r"(b1));
}

// ---------------- split-tf32 GEMM (fp32-accurate): C = A[R,64] @ W[64,NC] ---
template<int NC>
__global__ __launch_bounds__(256) void gemm_mma_kernel(
    const float* __restrict__ A, const float* __restrict__ W,
    const float* __restrict__ bias, float* __restrict__ Cout)
{
    constexpr int NHALF  = NC / 2;
    constexpr int NTILES = NHALF / 8;
    extern __shared__ float sm[];
    float* AsH = sm;                 // 64 x 68
    float* AsL = AsH + 64*68;
    float* WtH = AsL + 64*68;        // NC x 68  ([n][k])
    float* WtL = WtH + NC*68;
    int tid = threadIdx.x;
    int rowBase = blockIdx.x * 64;

    for (int i = tid; i < 64*64; i += 256) {
        int r = i >> 6, c = i & 63;
        float v = A[(rowBase + r)*64 + c];
        float hi = tf32r(v);
        AsH[r*68 + c] = hi;
        AsL[r*68 + c] = tf32r(v - hi);
    }
    for (int i = tid; i < 64*NC; i += 256) {
        int k = i / NC, n = i % NC;
        float v = W[i];
        float hi = tf32r(v);
        WtH[n*68 + k] = hi;
        WtL[n*68 + k] = tf32r(v - hi);
    }
    __syncthreads();

    int lane = tid & 31, w = tid >> 5;
    int gid = lane >> 2, tig = lane & 3;
    int mt = w & 3, nHalf = w >> 2;
    int rb = mt * 16;

    float acc[NTILES][4];
    #pragma unroll
    for (int nt = 0; nt < NTILES; nt++) {
        int colE = nHalf*NHALF + nt*8 + 2*tig;
        float be = bias ? bias[colE]   : 0.f;
        float bo = bias ? bias[colE+1] : 0.f;
        acc[nt][0] = be; acc[nt][1] = bo;
        acc[nt][2] = be; acc[nt][3] = bo;
    }
    #pragma unroll
    for (int kb = 0; kb < 8; kb++) {
        int k0 = kb * 8;
        unsigned ah[4], al[4];
        ah[0] = __float_as_uint(AsH[(rb + gid    )*68 + k0 + tig    ]);
        ah[1] = __float_as_uint(AsH[(rb + gid + 8)*68 + k0 + tig    ]);
        ah[2] = __float_as_uint(AsH[(rb + gid    )*68 + k0 + tig + 4]);
        ah[3] = __float_as_uint(AsH[(rb + gid + 8)*68 + k0 + tig + 4]);
        al[0] = __float_as_uint(AsL[(rb + gid    )*68 + k0 + tig    ]);
        al[1] = __float_as_uint(AsL[(rb + gid + 8)*68 + k0 + tig    ]);
        al[2] = __float_as_uint(AsL[(rb + gid    )*68 + k0 + tig + 4]);
        al[3] = __float_as_uint(AsL[(rb + gid + 8)*68 + k0 + tig + 4]);
        #pragma unroll
        for (int nt = 0; nt < NTILES; nt++) {
            int nb = nHalf*NHALF + nt*8;
            unsigned bh0 = __float_as_uint(WtH[(nb + gid)*68 + k0 + tig    ]);
            unsigned bh1 = __float_as_uint(WtH[(nb + gid)*68 + k0 + tig + 4]);
            unsigned bl0 = __float_as_uint(WtL[(nb + gid)*68 + k0 + tig    ]);
            unsigned bl1 = __float_as_uint(WtL[(nb + gid)*68 + k0 + tig + 4]);
            mma_tf32(acc[nt], ah, bh0, bh1);
            mma_tf32(acc[nt], ah, bl0, bl1);
            mma_tf32(acc[nt], al, bh0, bh1);
        }
    }
    #pragma unroll
    for (int nt = 0; nt < NTILES; nt++) {
        int colE = nHalf*NHALF + nt*8 + 2*tig;
        *(float2*)&Cout[(rowBase + rb + gid    )*NC + colE] = make_float2(acc[nt][0], acc[nt][1]);
        *(float2*)&Cout[(rowBase + rb + gid + 8)*NC + colE] = make_float2(acc[nt][2], acc[nt][3]);
    }
}

// ---------------- BN stats: one block per channel (deterministic) ----------
__global__ void bn_stats_kernel(const float* __restrict__ src)
{
    int c = blockIdx.x;
    float s1 = 0.f, s2 = 0.f;
    for (int r = threadIdx.x; r < NROWS; r += 256) {
        float v = src[r*64 + c];
        s1 += v; s2 += v*v;
    }
    __shared__ float sh1[256], sh2[256];
    sh1[threadIdx.x] = s1; sh2[threadIdx.x] = s2;
    __syncthreads();
    for (int st = 128; st > 0; st >>= 1) {
        if (threadIdx.x < st) {
            sh1[threadIdx.x] += sh1[threadIdx.x + st];
            sh2[threadIdx.x] += sh2[threadIdx.x + st];
        }
        __syncthreads();
    }
    if (threadIdx.x == 0) {
        float m = sh1[0] / (float)NROWS;
        float var = sh2[0] / (float)NROWS - m*m;
        g_mu[c] = m;
        g_rs[c] = rsqrtf(var + 1e-5f);
    }
}

// ---------------- BN apply + relu (+ optional residual add) ----------------
__global__ void bn_apply_kernel(const float* __restrict__ src,
                                const float* __restrict__ addsrc,
                                const float* __restrict__ gam,
                                const float* __restrict__ bet,
                                float* __restrict__ dst)
{
    int i = blockIdx.x * 256 + threadIdx.x;
    int c = i & 63;
    float v = (src[i] - g_mu[c]) * g_rs[c] * gam[c] + bet[c];
    v = fmaxf(v, 0.f);
    if (addsrc) v += addsrc[i];
    dst[i] = v;
}

// ---------------- brute-force KNN (float4 loads, per-lane top-8) ----------
__global__ __launch_bounds__(256) void knn_kernel(const float* __restrict__ p)
{
    int b = blockIdx.y;
    extern __shared__ float sh[];
    float* px = sh;
    float* py = sh + NPTS;
    float* pz = sh + 2*NPTS;
    float* sd = sh + 3*NPTS;           // 8 warps * 256 floats
    int*   si = (int*)(sd + 8*256);    // 8 warps * 256 ints
    const float* pb = p + b*NPTS*3;
    for (int i = threadIdx.x; i < NPTS; i += 256) {
        px[i] = pb[3*i];
        py[i] = pb[3*i + 1];
        pz[i] = pb[3*i + 2];
    }
    __syncthreads();
    int w = threadIdx.x >> 5, lane = threadIdx.x & 31;
    float* wd = sd + w*256;
    int*   wi = si + w*256;

    for (int qq = 0; qq < 4; qq++) {
        int n = blockIdx.x*32 + w*4 + qq;
        float qx = px[n], qy = py[n], qz = pz[n];
        float dk[8]; int ik[8];
        #pragma unroll
        for (int t = 0; t < 8; t++) { dk[t] = FLT_MAX; ik[t] = 0; }
        for (int it = 0; it < 32; it++) {
            int base = it*128 + lane*4;
            float4 x4 = *(const float4*)&px[base];
            float4 y4 = *(const float4*)&py[base];
            float4 z4 = *(const float4*)&pz[base];
            float d4[4];
            d4[0] = (x4.x-qx)*(x4.x-qx) + (y4.x-qy)*(y4.x-qy) + (z4.x-qz)*(z4.x-qz);
            d4[1] = (x4.y-qx)*(x4.y-qx) + (y4.y-qy)*(y4.y-qy) + (z4.y-qz)*(z4.y-qz);
            d4[2] = (x4.z-qx)*(x4.z-qx) + (y4.z-qy)*(y4.z-qy) + (z4.z-qz)*(z4.z-qz);
            d4[3] = (x4.w-qx)*(x4.w-qx) + (y4.w-qy)*(y4.w-qy) + (z4.w-qz)*(z4.w-qz);
            #pragma unroll
            for (int j = 0; j < 4; j++) {
                float d = d4[j];
                if (d < dk[7]) {
                    dk[7] = d; ik[7] = base + j;
                    #pragma unroll
                    for (int s = 7; s > 0; --s) {
                        if (dk[s] < dk[s-1]) {
                            float td = dk[s]; dk[s] = dk[s-1]; dk[s-1] = td;
                            int   ti = ik[s]; ik[s] = ik[s-1]; ik[s-1] = ti;
                        }
                    }
                }
            }
        }
        #pragma unroll
        for (int t = 0; t < 8; t++) {
            wd[lane*8 + t] = dk[t];
            wi[lane*8 + t] = ik[t];
        }
        __syncwarp();
        // merge 32 sorted lists of 8 -> global top-16
        int pos = 0;
        for (int t = 0; t < 16; t++) {
            float h = (pos < 8) ? wd[lane*8 + pos] : FLT_MAX;
            float v = h; int src = lane;
            #pragma unroll
            for (int off = 16; off > 0; off >>= 1) {
                float v2 = __shfl_down_sync(0xffffffffu, v, off);
                int   s2 = __shfl_down_sync(0xffffffffu, src, off);
                if (v2 < v || (v2 == v && s2 < src)) { v = v2; src = s2; }
            }
            src = __shfl_sync(0xffffffffu, src, 0);
            int wpos = __shfl_sync(0xffffffffu, pos, src);
            if (lane == 0) g_idx[((long)b*NPTS + n)*16 + t] = wi[src*8 + wpos];
            if (lane == src) pos++;
        }
        __syncwarp();
    }
}

// ---------------- pe-MLP (split-tf32 mma) + build T, vv --------------------
#define BT_SMEM ((96+32+64 + 4*2304 + 4352)*4)
__global__ __launch_bounds__(256) void build_t_kernel(
    const float* __restrict__ p,
    const float* __restrict__ w1, const float* __restrict__ b1,
    const float* __restrict__ w2, const float* __restrict__ b2)
{
    extern __shared__ float bsm[];
    float* pw1s = bsm;               // 96
    float* pb1s = pw1s + 96;         // 32
    float* pb2s = pb1s + 32;         // 64
    float* w2H  = pb2s + 64;         // 64*36 [n][k]
    float* w2L  = w2H + 2304;
    float* hidH = w2L + 2304;        // 64*36 [row][h]
    float* hidL = hidH + 2304;
    float* pes  = hidL + 2304;       // 64*68
    int tid = threadIdx.x;
    if (tid < 96) pw1s[tid] = w1[tid];
    if (tid < 32) pb1s[tid] = b1[tid];
    if (tid < 64) pb2s[tid] = b2[tid];
    for (int i = tid; i < 2048; i += 256) {
        int k = i >> 6, n = i & 63;
        float v = w2[i];
        float hi = tf32r(v);
        w2H[n*36 + k] = hi;
        w2L[n*36 + k] = tf32r(v - hi);
    }
    __syncthreads();

    int rid = tid >> 2;
    int row = blockIdx.x * 64 + rid;       // (b,n,j) flattened
    int q = row >> 4;                      // b*4096+n
    int b = q >> 12;
    int nb = (b << 12) + g_idx[row];       // b*4096 + neighbor

    float rx = p[q*3+0] - p[nb*3+0];
    float ry = p[q*3+1] - p[nb*3+1];
    float rz = p[q*3+2] - p[nb*3+2];

    {
        int h0 = (tid & 3) * 8;
        #pragma unroll
        for (int j = 0; j < 8; j++) {
            int h = h0 + j;
            float t = fmaxf(rx*pw1s[h] + ry*pw1s[32+h] + rz*pw1s[64+h] + pb1s[h], 0.f);
            float hi = tf32r(t);
            hidH[rid*36 + h] = hi;
            hidL[rid*36 + h] = tf32r(t - hi);
        }
    }
    __syncthreads();

    // pe = relu_hid @ pos_w2 + pos_b2  (split-tf32, K=32)
    {
        int lane = tid & 31, w = tid >> 5;
        int gid = lane >> 2, tig = lane & 3;
        int mt = w & 3, nHalf = w >> 2;
        int rb = mt * 16;
        float acc[4][4];
        #pragma unroll
        for (int nt = 0; nt < 4; nt++) {
            int colE = nHalf*32 + nt*8 + 2*tig;
            float be = pb2s[colE], bo = pb2s[colE+1];
            acc[nt][0] = be; acc[nt][1] = bo;
            acc[nt][2] = be; acc[nt][3] = bo;
        }
        #pragma unroll
        for (int kb = 0; kb < 4; kb++) {
            int k0 = kb * 8;
            unsigned ah[4], al[4];
            ah[0] = __float_as_uint(hidH[(rb + gid    )*36 + k0 + tig    ]);
            ah[1] = __float_as_uint(hidH[(rb + gid + 8)*36 + k0 + tig    ]);
            ah[2] = __float_as_uint(hidH[(rb + gid    )*36 + k0 + tig + 4]);
            ah[3] = __float_as_uint(hidH[(rb + gid + 8)*36 + k0 + tig + 4]);
            al[0] = __float_as_uint(hidL[(rb + gid    )*36 + k0 + tig    ]);
            al[1] = __float_as_uint(hidL[(rb + gid + 8)*36 + k0 + tig    ]);
            al[2] = __float_as_uint(hidL[(rb + gid    )*36 + k0 + tig + 4]);
            al[3] = __float_as_uint(hidL[(rb + gid + 8)*36 + k0 + tig + 4]);
            #pragma unroll
            for (int nt = 0; nt < 4; nt++) {
                int nbase = nHalf*32 + nt*8;
                unsigned bh0 = __float_as_uint(w2H[(nbase + gid)*36 + k0 + tig    ]);
                unsigned bh1 = __float_as_uint(w2H[(nbase + gid)*36 + k0 + tig + 4]);
                unsigned bl0 = __float_as_uint(w2L[(nbase + gid)*36 + k0 + tig    ]);
                unsigned bl1 = __float_as_uint(w2L[(nbase + gid)*36 + k0 + tig + 4]);
                mma_tf32(acc[nt], ah, bh0, bh1);
                mma_tf32(acc[nt], ah, bl0, bl1);
                mma_tf32(acc[nt], al, bh0, bh1);
            }
        }
        #pragma unroll
        for (int nt = 0; nt < 4; nt++) {
            int colE = nHalf*32 + nt*8 + 2*tig;
            *(float2*)&pes[(rb + gid    )*68 + colE] = make_float2(acc[nt][0], acc[nt][1]);
            *(float2*)&pes[(rb + gid + 8)*68 + colE] = make_float2(acc[nt][2], acc[nt][3]);
        }
    }
    __syncthreads();

    int ch = (tid & 3) * 16;
    #pragma unroll
    for (int v4 = 0; v4 < 4; v4++) {
        float4 t1 = *(const float4*)&g_qkv[q*192 + ch + v4*4];
        float4 t2 = *(const float4*)&g_qkv[nb*192 + 64 + ch + v4*4];
        float4 t3 = *(const float4*)&g_qkv[nb*192 + 128 + ch + v4*4];
        float4 pe = *(const float4*)&pes[rid*68 + ch + v4*4];
        float4 To = make_float4(t1.x - t2.x + pe.x, t1.y - t2.y + pe.y,
                                t1.z - t2.z + pe.z, t1.w - t2.w + pe.w);
        float4 Vo = make_float4(t3.x + pe.x, t3.y + pe.y,
                                t3.z + pe.z, t3.w + pe.w);
        *(float4*)&g_T [row*64 + ch + v4*4] = To;
        *(float4*)&g_vv[row*64 + ch + v4*4] = Vo;
    }
}

// ---------------- fused attention MLP (fp16 mma) + softmax + agg -----------
// float region: b1s[256], b2s[64]; half region follows.
#define AT_FBASE  320
#define W1T_H_OFF 0                         // [256][72] halfs
#define W2T_H_OFF (256*72)                  // [64][264]
#define TS_H_OFF  (W2T_H_OFF + 64*264)      // [64][72]
#define HS_H_OFF  (TS_H_OFF + 64*72)        // [64][264]
#define AT_HALFS  (HS_H_OFF + 64*264)
#define ATTN_SMEM (AT_FBASE*4 + AT_HALFS*2)

__global__ __launch_bounds__(256) void attn_fused_kernel(
    const float* __restrict__ W1, const float* __restrict__ B1,
    const float* __restrict__ W2, const float* __restrict__ B2,
    int tilesPerCta)
{
    extern __shared__ float sh[];
    float* b1s = sh;
    float* b2s = sh + 256;
    __half* hb  = (__half*)(sh + AT_FBASE);
    __half* w1t = hb + W1T_H_OFF;
    __half* w2t = hb + W2T_H_OFF;
    __half* ts  = hb + TS_H_OFF;
    __half* hs  = hb + HS_H_OFF;
    int tid = threadIdx.x;

    for (int i = tid; i < 64*256; i += 256) {
        int k = i >> 8, n = i & 255;
        w1t[n*72 + k] = __float2half(W1[i]);
    }
    for (int i = tid; i < 256*64; i += 256) {
        int k = i >> 6, n = i & 63;
        w2t[n*264 + k] = __float2half(W2[i]);
    }
    b1s[tid] = B1[tid];
    if (tid < 64) b2s[tid] = B2[tid];

    int lane = tid & 31, w = tid >> 5;
    int gid = lane >> 2, tig = lane & 3;
    int mPair  = w & 1;        // layer1: 2 m-tiles (32 rows)
    int nGroup = w >> 1;       // layer1: 64 cols
    int mt2    = w & 3;        // layer2: one query (16 rows)
    int nHalf  = w >> 2;       // layer2: 32 cols

    for (int t = 0; t < tilesPerCta; t++) {
        int rowBase = (blockIdx.x * tilesPerCta + t) * 64;
        __syncthreads();
        for (int i = tid; i < 1024; i += 256) {
            int r = i >> 4, c4 = (i & 15) * 4;
            float4 v = *(const float4*)&g_T[(rowBase + r)*64 + c4];
            *(__half2*)&ts[r*72 + c4    ] = __floats2half2_rn(v.x, v.y);
            *(__half2*)&ts[r*72 + c4 + 2] = __floats2half2_rn(v.z, v.w);
        }
        __syncthreads();

        // ---------- layer 1: H = relu(T @ W1 + b1), K=64 (4 k16 steps) -----
        float acc1[2][8][4];
        #pragma unroll
        for (int mt = 0; mt < 2; mt++)
            #pragma unroll
            for (int nt = 0; nt < 8; nt++) {
                int colE = nGroup*64 + nt*8 + 2*tig;
                float be = b1s[colE], bo = b1s[colE + 1];
                acc1[mt][nt][0] = be; acc1[mt][nt][1] = bo;
                acc1[mt][nt][2] = be; acc1[mt][nt][3] = bo;
            }
        #pragma unroll
        for (int kb = 0; kb < 4; kb++) {
            int k0 = kb * 16;
            unsigned a[2][4];
            #pragma unroll
            for (int mt = 0; mt < 2; mt++) {
                int rb = mPair*32 + mt*16;
                a[mt][0] = *(unsigned*)&ts[(rb + gid    )*72 + k0 + 2*tig    ];
                a[mt][1] = *(unsigned*)&ts[(rb + gid + 8)*72 + k0 + 2*tig    ];
                a[mt][2] = *(unsigned*)&ts[(rb + gid    )*72 + k0 + 2*tig + 8];
                a[mt][3] = *(unsigned*)&ts[(rb + gid + 8)*72 + k0 + 2*tig + 8];
            }
            #pragma unroll
            for (int nt = 0; nt < 8; nt++) {
                int nb = nGroup*64 + nt*8;
                unsigned b0 = *(unsigned*)&w1t[(nb + gid)*72 + k0 + 2*tig    ];
                unsigned b1 = *(unsigned*)&w1t[(nb + gid)*72 + k0 + 2*tig + 8];
                mma_f16(acc1[0][nt], a[0], b0, b1);
                mma_f16(acc1[1][nt], a[1], b0, b1);
            }
        }
        #pragma unroll
        for (int mt = 0; mt < 2; mt++) {
            int rb = mPair*32 + mt*16;
            #pragma unroll
            for (int nt = 0; nt < 8; nt++) {
                int colE = nGroup*64 + nt*8 + 2*tig;
                *(__half2*)&hs[(rb + gid    )*264 + colE] =
                    __floats2half2_rn(fmaxf(acc1[mt][nt][0], 0.f), fmaxf(acc1[mt][nt][1], 0.f));
                *(__half2*)&hs[(rb + gid + 8)*264 + colE] =
                    __floats2half2_rn(fmaxf(acc1[mt][nt][2], 0.f), fmaxf(acc1[mt][nt][3], 0.f));
            }
        }
        __syncthreads();

        // ---------- layer 2: sim = H @ W2 + b2, K=256 (16 k16 steps) -------
        float acc2[4][4];
        #pragma unroll
        for (int nt = 0; nt < 4; nt++) {
            int colE = nHalf*32 + nt*8 + 2*tig;
            float be = b2s[colE], bo = b2s[colE + 1];
            acc2[nt][0] = be; acc2[nt][1] = bo;
            acc2[nt][2] = be; acc2[nt][3] = bo;
        }
        int rb2 = mt2 * 16;
        #pragma unroll 4
        for (int kb = 0; kb < 16; kb++) {
            int k0 = kb * 16;
            unsigned a[4];
            a[0] = *(unsigned*)&hs[(rb2 + gid    )*264 + k0 + 2*tig    ];
            a[1] = *(unsigned*)&hs[(rb2 + gid + 8)*264 + k0 + 2*tig    ];
            a[2] = *(unsigned*)&hs[(rb2 + gid    )*264 + k0 + 2*tig + 8];
            a[3] = *(unsigned*)&hs[(rb2 + gid + 8)*264 + k0 + 2*tig + 8];
            #pragma unroll
            for (int nt = 0; nt < 4; nt++) {
                int nb = nHalf*32 + nt*8;
                unsigned b0 = *(unsigned*)&w2t[(nb + gid)*264 + k0 + 2*tig    ];
                unsigned b1 = *(unsigned*)&w2t[(nb + gid)*264 + k0 + 2*tig + 8];
                mma_f16(acc2[nt], a, b0, b1);
            }
        }

        // ---------- softmax over 16 neighbors + aggregation ----------
        int qrow = rowBase + mt2*16;
        int qout = (rowBase >> 4) + mt2;
        #pragma unroll
        for (int nt = 0; nt < 4; nt++) {
            int colE = nHalf*32 + nt*8 + 2*tig;
            float me = fmaxf(acc2[nt][0], acc2[nt][2]);
            float mo = fmaxf(acc2[nt][1], acc2[nt][3]);
            #pragma unroll
            for (int off = 4; off < 32; off <<= 1) {
                me = fmaxf(me, __shfl_xor_sync(0xffffffffu, me, off));
                mo = fmaxf(mo, __shfl_xor_sync(0xffffffffu, mo, off));
            }
            float e0 = __expf(acc2[nt][0] - me);
            float e1 = __expf(acc2[nt][1] - mo);
            float e2 = __expf(acc2[nt][2] - me);
            float e3 = __expf(acc2[nt][3] - mo);

            float2 v0 = *(const float2*)&g_vv[(qrow + gid    )*64 + colE];
            float2 v1 = *(const float2*)&g_vv[(qrow + gid + 8)*64 + colE];

            float se = e0 + e2;
            float so = e1 + e3;
            float pe = e0*v0.x + e2*v1.x;
            float po = e1*v0.y + e3*v1.y;
            #pragma unroll
            for (int off = 4; off < 32; off <<= 1) {
                se += __shfl_xor_sync(0xffffffffu, se, off);
                so += __shfl_xor_sync(0xffffffffu, so, off);
                pe += __shfl_xor_sync(0xffffffffu, pe, off);
                po += __shfl_xor_sync(0xffffffffu, po, off);
            }
            if (gid == 0) {
                float2 outv = make_float2(pe / se, po / so);
                *(float2*)&g_agg[qout*64 + colE] = outv;
            }
        }
    }
}

// ---------------- copy p into output tail ---------------------------------
__global__ void finalize_p_kernel(const float* __restrict__ p, float* __restrict__ out)
{
    int i = blockIdx.x * 256 + threadIdx.x;
    out[i] = p[i];
}

// ---------------- launch ---------------------------------------------------
extern "C" void kernel_launch(void* const* d_in, const int* in_sizes, int n_in,
                              void* d_out, int out_size)
{
    const float* x      = (const float*)d_in[0];
    const float* p      = (const float*)d_in[1];
    const float* fc1_w  = (const float*)d_in[2];
    const float* fc1_b  = (const float*)d_in[3];
    const float* bn1_g  = (const float*)d_in[4];
    const float* bn1_b  = (const float*)d_in[5];
    const float* qkv_w  = (const float*)d_in[6];
    const float* pos_w1 = (const float*)d_in[7];
    const float* pos_b1 = (const float*)d_in[8];
    const float* pos_w2 = (const float*)d_in[9];
    const float* pos_b2 = (const float*)d_in[10];
    const float* attn_w1= (const float*)d_in[11];
    const float* attn_b1= (const float*)d_in[12];
    const float* attn_w2= (const float*)d_in[13];
    const float* attn_b2= (const float*)d_in[14];
    const float* bn2_g  = (const float*)d_in[15];
    const float* bn2_b  = (const float*)d_in[16];
    const float* fc2_w  = (const float*)d_in[17];
    const float* fc2_b  = (const float*)d_in[18];
    const float* bn3_g  = (const float*)d_in[19];
    const float* bn3_b  = (const float*)d_in[20];
    float* out = (float*)d_out;

    float *hpre, *h, *qkv, *agg, *u, *ypre;
    cudaGetSymbolAddress((void**)&hpre, g_hpre);
    cudaGetSymbolAddress((void**)&h,    g_h);
    cudaGetSymbolAddress((void**)&qkv,  g_qkv);
    cudaGetSymbolAddress((void**)&agg,  g_agg);
    cudaGetSymbolAddress((void**)&u,    g_u);
    cudaGetSymbolAddress((void**)&ypre, g_ypre);

    const int SMEM_G64  = (64*68*2 + 64*68*2 ) * 4;   // ~70 KB
    const int SMEM_G192 = (64*68*2 + 192*68*2) * 4;   // ~139 KB
    const int SMEM_KNN  = (3*NPTS + 8*256)*4 + 8*256*4;
    cudaFuncSetAttribute(knn_kernel, cudaFuncAttributeMaxDynamicSharedMemorySize, SMEM_KNN);
    cudaFuncSetAttribute(attn_fused_kernel, cudaFuncAttributeMaxDynamicSharedMemorySize, ATTN_SMEM);
    cudaFuncSetAttribute(build_t_kernel, cudaFuncAttributeMaxDynamicSharedMemorySize, BT_SMEM);
    cudaFuncSetAttribute(gemm_mma_kernel<64>,  cudaFuncAttributeMaxDynamicSharedMemorySize, SMEM_G64);
    cudaFuncSetAttribute(gemm_mma_kernel<192>, cudaFuncAttributeMaxDynamicSharedMemorySize, SMEM_G192);

    // fc1 -> bn1 -> relu (h = residual)
    gemm_mma_kernel<64><<<256, 256, SMEM_G64>>>(x, fc1_w, fc1_b, hpre);
    bn_stats_kernel<<<64, 256>>>(hpre);
    bn_apply_kernel<<<4096, 256>>>(hpre, nullptr, bn1_g, bn1_b, h);

    // qkv projection (no bias)
    gemm_mma_kernel<192><<<256, 256, SMEM_G192>>>(h, qkv_w, nullptr, qkv);

    // KNN (per batch)
    knn_kernel<<<dim3(128,4), 256, SMEM_KNN>>>(p);

    // pe-MLP (split-tf32 mma) + T/vv
    build_t_kernel<<<4096, 256, BT_SMEM>>>(p, pos_w1, pos_b1, pos_w2, pos_b2);

    // fused attention MLP (fp16 mma) + softmax + aggregation
    attn_fused_kernel<<<1024, 256, ATTN_SMEM>>>(attn_w1, attn_b1, attn_w2, attn_b2, 4);

    // bn2 -> relu -> + residual
    bn_stats_kernel<<<64, 256>>>(agg);
    bn_apply_kernel<<<4096, 256>>>(agg, h, bn2_g, bn2_b, u);

    // fc2 -> bn3 -> relu -> output
    gemm_mma_kernel<64><<<256, 256, SMEM_G64>>>(u, fc2_w, fc2_b, ypre);
    bn_stats_kernel<<<64, 256>>>(ypre);
    bn_apply_kernel<<<4096, 256>>>(ypre, nullptr, bn3_g, bn3_b, out);

    // output tail: p passthrough
    finalize_p_kernel<<<192, 256>>>(p, out + NROWS*64);
}